// round 4
// baseline (speedup 1.0000x reference)
#include <cuda_runtime.h>
#include <cuda_bf16.h>

#define NFFT   16384
#define LOGN   14
#define LSEQ   8192
#define NT     512
#define DCH    256
#define NROWS  2048

// Twiddle table: W^k = exp(-2*pi*i*k/NFFT); only k < 512 is used by the FFT.
__device__ float2 d_tw[NFFT / 2];
// Precomputed output mask (B x L), 1.0 where positions != -1
__device__ float d_mask[8 * LSEQ];

// Combined setup: twiddles + positions dtype detection + mask.
__global__ void setup_kernel(const int* __restrict__ pos32) {
    int i = blockIdx.x * blockDim.x + threadIdx.x;   // 0 .. 65535
    if (i < NFFT / 2) {
        double a = -2.0 * 3.141592653589793238462643383279502884 * (double)i / (double)NFFT;
        d_tw[i] = make_float2((float)cos(a), (float)sin(a));
    }
    // int64 vs int32 detection (jax x64 may be off): int64 high words are 0/-1.
    bool is64 = true;
    #pragma unroll
    for (int j = 0; j < 64; j++) {
        int hi = __ldg(pos32 + 2 * j + 1);
        if (hi != 0 && hi != -1) is64 = false;
    }
    bool valid;
    if (is64) valid = (((const long long*)pos32)[i] != -1LL);
    else      valid = (pos32[i] != -1);
    d_mask[i] = valid ? 1.0f : 0.0f;
}

__device__ __forceinline__ float2 cmul(float2 a, float2 b) {
    return make_float2(fmaf(a.x, b.x, -a.y * b.y), fmaf(a.x, b.y, a.y * b.x));
}
// a * conj(b)
__device__ __forceinline__ float2 cmulc(float2 a, float2 b) {
    return make_float2(fmaf(a.x, b.x,  a.y * b.y), fmaf(a.y, b.x, -a.x * b.y));
}
__device__ __forceinline__ float2 mi(float2 z) { return make_float2(z.y, -z.x); }   // z * (-i)
// Swizzle: conflict-free per 16-lane LDS.64 phase for strides 512, 16, 1 and pointwise.
__device__ __forceinline__ int sw(int i) { return i ^ ((i >> 5) & 31); }

// W32(k) = exp(-2*pi*i*k/32), k = 1..15 (compile-time immediates via switch)
__device__ __forceinline__ float2 W32k(int k) {
    switch (k) {
    case 1:  return make_float2( 0.980785280403230449f, -0.195090322016128268f);
    case 2:  return make_float2( 0.923879532511286756f, -0.382683432365089772f);
    case 3:  return make_float2( 0.831469612302545237f, -0.555570233019602225f);
    case 4:  return make_float2( 0.707106781186547524f, -0.707106781186547524f);
    case 5:  return make_float2( 0.555570233019602225f, -0.831469612302545237f);
    case 6:  return make_float2( 0.382683432365089772f, -0.923879532511286756f);
    case 7:  return make_float2( 0.195090322016128268f, -0.980785280403230449f);
    case 9:  return make_float2(-0.195090322016128268f, -0.980785280403230449f);
    case 10: return make_float2(-0.382683432365089772f, -0.923879532511286756f);
    case 11: return make_float2(-0.555570233019602225f, -0.831469612302545237f);
    case 12: return make_float2(-0.707106781186547524f, -0.707106781186547524f);
    case 13: return make_float2(-0.831469612302545237f, -0.555570233019602225f);
    case 14: return make_float2(-0.923879532511286756f, -0.382683432365089772f);
    case 15: return make_float2(-0.980785280403230449f, -0.195090322016128268f);
    default: return make_float2(1.0f, 0.0f);
    }
}
// wp * W32(k), k compile-time
__device__ __forceinline__ float2 tw32(float2 wp, int k) {
    if (k == 0) return wp;
    if (k == 8) return mi(wp);
    return cmul(wp, W32k(k));
}

// DIF butterfly: a' = a+b ; b' = (a-b)*tw
__device__ __forceinline__ void bf(float2& a, float2& b, float2 tw) {
    float2 s = make_float2(a.x + b.x, a.y + b.y);
    float2 d = make_float2(a.x - b.x, a.y - b.y);
    a = s; b = cmul(d, tw);
}
// DIT butterfly: t = b*conj(tw) ; a' = a+t ; b' = a-t
__device__ __forceinline__ void bfi(float2& a, float2& b, float2 tw) {
    float2 t = cmulc(b, tw);
    float2 s = make_float2(a.x + t.x, a.y + t.y);
    b = make_float2(a.x - t.x, a.y - t.y);
    a = s;
}
// DIF butterfly with constant twiddle W32(k), k compile-time (0/8 special-cased)
__device__ __forceinline__ void bfc(float2& a, float2& b, int k) {
    float2 s = make_float2(a.x + b.x, a.y + b.y);
    float2 d = make_float2(a.x - b.x, a.y - b.y);
    a = s;
    if (k == 0)       b = d;
    else if (k == 8)  b = mi(d);
    else              b = cmul(d, W32k(k));
}
// DIT butterfly with conj(W32(k))
__device__ __forceinline__ void bfic(float2& a, float2& b, int k) {
    float2 t;
    if (k == 0)       t = b;
    else if (k == 8)  t = make_float2(-b.y, b.x);   // b * conj(-i) = b * i
    else              t = cmulc(b, W32k(k));
    float2 s = make_float2(a.x + t.x, a.y + t.y);
    b = make_float2(a.x - t.x, a.y - t.y);
    a = s;
}

// Forward 5-stage group over 32 register elements, base twiddle w (dist 16..1).
__device__ __forceinline__ void dif5(float2 v[32], float2 w) {
    float2 wp = w;
    #pragma unroll
    for (int u = 0; u < 5; u++) {
        const int h = 16 >> u, nb = 1 << u;
        #pragma unroll
        for (int bb = 0; bb < nb; bb++) {
            #pragma unroll
            for (int m = 0; m < h; m++) {
                int j0 = bb * 2 * h + m, j1 = j0 + h;
                bf(v[j0], v[j1], tw32(wp, m << u));
            }
        }
        if (u < 4) wp = cmul(wp, wp);
    }
}
// Same, first stage degenerate because v[16..31] == 0 (zero padding).
__device__ __forceinline__ void dif5_zero(float2 v[32], float2 w) {
    #pragma unroll
    for (int m = 0; m < 16; m++) v[m + 16] = cmul(v[m], tw32(w, m));
    float2 wp = cmul(w, w);
    #pragma unroll
    for (int u = 1; u < 5; u++) {
        const int h = 16 >> u, nb = 1 << u;
        #pragma unroll
        for (int bb = 0; bb < nb; bb++) {
            #pragma unroll
            for (int m = 0; m < h; m++) {
                int j0 = bb * 2 * h + m, j1 = j0 + h;
                bf(v[j0], v[j1], tw32(wp, m << u));
            }
        }
        if (u < 4) wp = cmul(wp, wp);
    }
}
// Inverse 5-stage group (dist 1..16), conj twiddles.
__device__ __forceinline__ void dit5(float2 v[32], float2 w) {
    float2 wp0 = w;
    float2 wp1 = cmul(wp0, wp0);
    float2 wp2 = cmul(wp1, wp1);
    float2 wp3 = cmul(wp2, wp2);
    float2 wp4 = cmul(wp3, wp3);
    #pragma unroll
    for (int u = 0; u < 5; u++) {
        const int h = 1 << u, nb = 16 >> u;
        float2 base = (u == 0) ? wp4 : (u == 1) ? wp3 : (u == 2) ? wp2 : (u == 3) ? wp1 : wp0;
        #pragma unroll
        for (int bb = 0; bb < nb; bb++) {
            #pragma unroll
            for (int m = 0; m < h; m++) {
                int j0 = bb * 2 * h + m, j1 = j0 + h;
                bfi(v[j0], v[j1], tw32(base, m << (4 - u)));
            }
        }
    }
}
// Forward stages at dist 8,4,2,1 over 16 contiguous elements; pure-constant twiddles.
__device__ __forceinline__ void dif4c(float2* v) {
    #pragma unroll
    for (int m = 0; m < 8; m++) bfc(v[m], v[m + 8], 2 * m);
    #pragma unroll
    for (int bb = 0; bb < 2; bb++)
        #pragma unroll
        for (int m = 0; m < 4; m++) bfc(v[8 * bb + m], v[8 * bb + m + 4], 4 * m);
    #pragma unroll
    for (int bb = 0; bb < 4; bb++)
        #pragma unroll
        for (int m = 0; m < 2; m++) bfc(v[4 * bb + m], v[4 * bb + m + 2], 8 * m);
    #pragma unroll
    for (int bb = 0; bb < 8; bb++) bfc(v[2 * bb], v[2 * bb + 1], 0);
}
// Inverse stages at dist 1,2,4,8 over 16 contiguous elements.
__device__ __forceinline__ void dit4c(float2* v) {
    #pragma unroll
    for (int bb = 0; bb < 8; bb++) bfic(v[2 * bb], v[2 * bb + 1], 0);
    #pragma unroll
    for (int bb = 0; bb < 4; bb++)
        #pragma unroll
        for (int m = 0; m < 2; m++) bfic(v[4 * bb + m], v[4 * bb + m + 2], 8 * m);
    #pragma unroll
    for (int bb = 0; bb < 2; bb++)
        #pragma unroll
        for (int m = 0; m < 4; m++) bfic(v[8 * bb + m], v[8 * bb + m + 4], 4 * m);
    #pragma unroll
    for (int m = 0; m < 8; m++) bfic(v[m], v[m + 8], 2 * m);
}

extern "C" __global__ void __launch_bounds__(NT, 1)
fftconv_kernel(const float* __restrict__ x, const float* __restrict__ f,
               float* __restrict__ out) {
    extern __shared__ float2 sm[];   // NFFT float2 = 128 KB
    const int row = blockIdx.x;
    const int b   = row / DCH;
    const int t   = threadIdx.x;
    const float* __restrict__ xr = x + (size_t)row * LSEQ;
    const float* __restrict__ fr = f + (size_t)row * LSEQ;

    float2 v[32];

    // ---- Load (pattern e = t + 512j, j<16), pack z = x + i*f; upper half zero ----
    #pragma unroll
    for (int j = 0; j < 16; j++) {
        int e = t + 512 * j;
        v[j] = make_float2(xr[e], fr[e]);
    }

    // ---- Forward FFT (DIF, natural -> bit-reversed) ----
    dif5_zero(v, d_tw[t]);                              // stages 0-4, stride 512
    #pragma unroll
    for (int j = 0; j < 32; j++) sm[sw(t + 512 * j)] = v[j];
    __syncthreads();
    {
        int g = t >> 4, r = t & 15, base = g * 512 + r;
        #pragma unroll
        for (int j = 0; j < 32; j++) v[j] = sm[sw(base + 16 * j)];
        dif5(v, d_tw[r << 5]);                          // stages 5-9, stride 16
        #pragma unroll
        for (int j = 0; j < 32; j++) sm[sw(base + 16 * j)] = v[j];
    }
    __syncthreads();
    {
        int base = t * 32;
        #pragma unroll
        for (int j = 0; j < 32; j++) v[j] = sm[sw(base + j)];
        dif4c(v); dif4c(v + 16);                        // stages 10-13, stride 1
        #pragma unroll
        for (int j = 0; j < 32; j++) sm[sw(base + j)] = v[j];
    }
    __syncthreads();

    // ---- Pointwise in bit-reversed domain: two-for-one split + product ----
    // Lanes own HIGH bits of k so brev(k) varies in LOW bits -> conflict-free phases.
    const float scale = 1.0f / ((float)NFFT * (float)NFFT);
    {
        int lane = t & 31, wrp = t >> 5;
        #pragma unroll
        for (int m = 0; m < 16; m++) {
            int k  = lane * 256 + wrp * 16 + m;          // covers 0..8191 exactly once
            int kk = (NFFT - k) & (NFFT - 1);
            int p1 = sw(__brev(k)  >> (32 - LOGN));
            int p2 = sw(__brev(kk) >> (32 - LOGN));
            float2 z1 = sm[p1];
            float2 z2 = sm[p2];
            float2 X = make_float2(0.5f * (z1.x + z2.x), 0.5f * (z1.y - z2.y));
            float2 F = make_float2(0.5f * (z1.y + z2.y), 0.5f * (z2.x - z1.x));
            float2 Y = cmul(X, F);
            Y.x *= scale; Y.y *= scale;
            sm[p1] = Y;
            sm[p2] = make_float2(Y.x, -Y.y);
        }
        if (t == 0) {                                    // k = 8192 self-pair, brev = 1
            int p = sw(1);
            float2 z = sm[p];
            sm[p] = make_float2(z.x * z.y * scale, 0.0f);
        }
    }
    __syncthreads();

    // ---- Inverse FFT (DIT, bit-reversed -> natural, unnormalized) ----
    {
        int base = t * 32;
        #pragma unroll
        for (int j = 0; j < 32; j++) v[j] = sm[sw(base + j)];
        dit4c(v); dit4c(v + 16);                        // stages 0-3, stride 1
        #pragma unroll
        for (int j = 0; j < 32; j++) sm[sw(base + j)] = v[j];
    }
    __syncthreads();
    {
        int g = t >> 4, r = t & 15, base = g * 512 + r;
        #pragma unroll
        for (int j = 0; j < 32; j++) v[j] = sm[sw(base + 16 * j)];
        dit5(v, d_tw[r << 5]);                          // stages 4-8, stride 16
        #pragma unroll
        for (int j = 0; j < 32; j++) sm[sw(base + 16 * j)] = v[j];
    }
    __syncthreads();
    {
        #pragma unroll
        for (int j = 0; j < 32; j++) v[j] = sm[sw(t + 512 * j)];
        dit5(v, d_tw[t]);                               // stages 9-13, stride 512

        // ---- Store first LSEQ real samples (e = t + 512j, j < 16), masked ----
        #pragma unroll
        for (int j = 0; j < 16; j++) {
            int l = t + 512 * j;
            out[(size_t)row * LSEQ + l] = d_mask[b * LSEQ + l] * v[j].x;
        }
    }
}

extern "C" void kernel_launch(void* const* d_in, const int* in_sizes, int n_in,
                              void* d_out, int out_size) {
    const float* x   = (const float*)d_in[0];
    const float* f   = (const float*)d_in[1];
    const int*   pos = (const int*)d_in[2];
    float*       out = (float*)d_out;

    cudaFuncSetAttribute(fftconv_kernel,
                         cudaFuncAttributeMaxDynamicSharedMemorySize,
                         NFFT * sizeof(float2));

    setup_kernel<<<(8 * LSEQ) / 256, 256>>>(pos);
    fftconv_kernel<<<NROWS, NT, NFFT * sizeof(float2)>>>(x, f, out);
}

// round 5
// speedup vs baseline: 2.3780x; 2.3780x over previous
#include <cuda_runtime.h>
#include <cuda_bf16.h>

#define NFFT   16384
#define LOGN   14
#define LSEQ   8192
#define NT     1024
#define DCH    256
#define NROWS  2048

// Twiddle table: W^k = exp(-2*pi*i*k/NFFT), k in [0, NFFT/2)
__device__ float2 d_tw[NFFT / 2];
// Precomputed output mask (B x L), 1.0 where positions != -1
__device__ float d_mask[8 * LSEQ];

// Combined setup: twiddles + positions dtype detection + mask.
__global__ void setup_kernel(const int* __restrict__ pos32) {
    int i = blockIdx.x * blockDim.x + threadIdx.x;   // 0 .. 65535
    if (i < NFFT / 2) {
        double a = -2.0 * 3.141592653589793238462643383279502884 * (double)i / (double)NFFT;
        d_tw[i] = make_float2((float)cos(a), (float)sin(a));
    }
    bool is64 = true;
    #pragma unroll
    for (int j = 0; j < 64; j++) {
        int hi = __ldg(pos32 + 2 * j + 1);
        if (hi != 0 && hi != -1) is64 = false;
    }
    bool valid;
    if (is64) valid = (((const long long*)pos32)[i] != -1LL);
    else      valid = (pos32[i] != -1);
    d_mask[i] = valid ? 1.0f : 0.0f;
}

__device__ __forceinline__ float2 cmul(float2 a, float2 b) {
    return make_float2(fmaf(a.x, b.x, -a.y * b.y), fmaf(a.x, b.y, a.y * b.x));
}
// a * conj(b)
__device__ __forceinline__ float2 cmulc(float2 a, float2 b) {
    return make_float2(fmaf(a.x, b.x,  a.y * b.y), fmaf(a.y, b.x, -a.x * b.y));
}
__device__ __forceinline__ float2 mi(float2 z) { return make_float2(z.y, -z.x); }  // z * (-i)
__device__ __forceinline__ int sw(int i) { return i ^ ((i >> 4) & 15); }

#define C16_1 make_float2(0.923879532511286756f, -0.382683432365089772f)
#define C16_2 make_float2(0.707106781186547524f, -0.707106781186547524f)
#define C16_3 make_float2(0.382683432365089772f, -0.923879532511286756f)

// DIF butterfly: a' = a+b ; b' = (a-b)*tw
__device__ __forceinline__ void bf(float2& a, float2& b, float2 tw) {
    float2 s = make_float2(a.x + b.x, a.y + b.y);
    float2 d = make_float2(a.x - b.x, a.y - b.y);
    a = s; b = cmul(d, tw);
}
// DIT butterfly: t = b*conj(tw) ; a' = a+t ; b' = a-t
__device__ __forceinline__ void bfi(float2& a, float2& b, float2 tw) {
    float2 t = cmulc(b, tw);
    float2 s = make_float2(a.x + t.x, a.y + t.y);
    b = make_float2(a.x - t.x, a.y - t.y);
    a = s;
}

// Forward stages at local distances 4, 2, 1 (shared tail of a radix-16 group).
__device__ __forceinline__ void dif_stages123(float2 v[16], float2 ws2) {
    float2 u = cmul(ws2, C16_2);
    bf(v[0], v[4],  ws2); bf(v[1], v[5],  u); bf(v[2],  v[6],  mi(ws2)); bf(v[3],  v[7],  mi(u));
    bf(v[8], v[12], ws2); bf(v[9], v[13], u); bf(v[10], v[14], mi(ws2)); bf(v[11], v[15], mi(u));
    float2 ws4 = cmul(ws2, ws2);
    #pragma unroll
    for (int b = 0; b < 4; b++) {
        bf(v[4*b],   v[4*b+2], ws4);
        bf(v[4*b+1], v[4*b+3], mi(ws4));
    }
    float2 ws8 = cmul(ws4, ws4);
    #pragma unroll
    for (int b = 0; b < 8; b++) bf(v[2*b], v[2*b+1], ws8);
}

// Full 4-stage forward group, base twiddle w (distances 8,4,2,1).
__device__ __forceinline__ void dif4(float2 v[16], float2 w) {
    float2 w1 = cmul(w, C16_1), w2 = cmul(w, C16_2), w3 = cmul(w, C16_3);
    bf(v[0], v[8],  w);     bf(v[1], v[9],  w1);     bf(v[2], v[10], w2);     bf(v[3], v[11], w3);
    bf(v[4], v[12], mi(w)); bf(v[5], v[13], mi(w1)); bf(v[6], v[14], mi(w2)); bf(v[7], v[15], mi(w3));
    dif_stages123(v, cmul(w, w));
}

// First forward group with v[8..15] == 0 (zero-padding): stage 0 degenerates.
__device__ __forceinline__ void dif4_zero(float2 v[16], float2 w) {
    float2 w1 = cmul(w, C16_1), w2 = cmul(w, C16_2), w3 = cmul(w, C16_3);
    v[8]  = cmul(v[0], w);      v[9]  = cmul(v[1], w1);
    v[10] = cmul(v[2], w2);     v[11] = cmul(v[3], w3);
    v[12] = cmul(v[4], mi(w));  v[13] = cmul(v[5], mi(w1));
    v[14] = cmul(v[6], mi(w2)); v[15] = cmul(v[7], mi(w3));
    dif_stages123(v, cmul(w, w));
}

// Full 4-stage inverse group, base twiddle w (distances 1,2,4,8), conj twiddles.
__device__ __forceinline__ void dit4(float2 v[16], float2 w) {
    float2 ws2 = cmul(w, w), ws4 = cmul(ws2, ws2), ws8 = cmul(ws4, ws4);
    #pragma unroll
    for (int b = 0; b < 8; b++) bfi(v[2*b], v[2*b+1], ws8);
    #pragma unroll
    for (int b = 0; b < 4; b++) {
        bfi(v[4*b],   v[4*b+2], ws4);
        bfi(v[4*b+1], v[4*b+3], mi(ws4));
    }
    float2 u = cmul(ws2, C16_2);
    bfi(v[0], v[4],  ws2); bfi(v[1], v[5],  u); bfi(v[2],  v[6],  mi(ws2)); bfi(v[3],  v[7],  mi(u));
    bfi(v[8], v[12], ws2); bfi(v[9], v[13], u); bfi(v[10], v[14], mi(ws2)); bfi(v[11], v[15], mi(u));
    float2 w1 = cmul(w, C16_1), w2 = cmul(w, C16_2), w3 = cmul(w, C16_3);
    bfi(v[0], v[8],  w);     bfi(v[1], v[9],  w1);     bfi(v[2], v[10], w2);     bfi(v[3], v[11], w3);
    bfi(v[4], v[12], mi(w)); bfi(v[5], v[13], mi(w1)); bfi(v[6], v[14], mi(w2)); bfi(v[7], v[15], mi(w3));
}

// Forward stages 12,13 on a contiguous 4-block: dist 2 (tw {1,-i}) then dist 1 (tw 1).
__device__ __forceinline__ void dif2(float2 v[4]) {
    { float2 s = make_float2(v[0].x + v[2].x, v[0].y + v[2].y);
      float2 d = make_float2(v[0].x - v[2].x, v[0].y - v[2].y);
      v[0] = s; v[2] = d; }
    { float2 s = make_float2(v[1].x + v[3].x, v[1].y + v[3].y);
      float2 d = make_float2(v[1].x - v[3].x, v[1].y - v[3].y);
      v[1] = s; v[3] = mi(d); }
    { float2 s = make_float2(v[0].x + v[1].x, v[0].y + v[1].y);
      float2 d = make_float2(v[0].x - v[1].x, v[0].y - v[1].y);
      v[0] = s; v[1] = d; }
    { float2 s = make_float2(v[2].x + v[3].x, v[2].y + v[3].y);
      float2 d = make_float2(v[2].x - v[3].x, v[2].y - v[3].y);
      v[2] = s; v[3] = d; }
}
// Inverse stages 0,1 on a contiguous 4-block: dist 1 (tw 1) then dist 2 (tw {1,+i}).
__device__ __forceinline__ void dit2(float2 v[4]) {
    { float2 s = make_float2(v[0].x + v[1].x, v[0].y + v[1].y);
      float2 d = make_float2(v[0].x - v[1].x, v[0].y - v[1].y);
      v[0] = s; v[1] = d; }
    { float2 s = make_float2(v[2].x + v[3].x, v[2].y + v[3].y);
      float2 d = make_float2(v[2].x - v[3].x, v[2].y - v[3].y);
      v[2] = s; v[3] = d; }
    { float2 s = make_float2(v[0].x + v[2].x, v[0].y + v[2].y);
      float2 d = make_float2(v[0].x - v[2].x, v[0].y - v[2].y);
      v[0] = s; v[2] = d; }
    { float2 t = make_float2(-v[3].y, v[3].x);              // v3 * (+i) = * conj(-i)
      float2 s = make_float2(v[1].x + t.x, v[1].y + t.y);
      float2 d = make_float2(v[1].x - t.x, v[1].y - t.y);
      v[1] = s; v[3] = d; }
}
// Pointwise pair: za = Z[k], zb = Z[N-k]  ->  za = Y(k), zb = conj(Y(k)).
__device__ __forceinline__ void pw(float2& za, float2& zb, float scale) {
    float2 z1 = za, z2 = zb;
    float2 X = make_float2(0.5f * (z1.x + z2.x), 0.5f * (z1.y - z2.y));
    float2 F = make_float2(0.5f * (z1.y + z2.y), 0.5f * (z2.x - z1.x));
    float2 Y = cmul(X, F);
    Y.x *= scale; Y.y *= scale;
    za = Y; zb = make_float2(Y.x, -Y.y);
}
// Self-paired bin (k == N-k): Y = Re(z)*Im(z)*scale, purely real.
__device__ __forceinline__ void pws(float2& z, float scale) {
    z = make_float2(z.x * z.y * scale, 0.0f);
}

extern "C" __global__ void __launch_bounds__(NT, 1)
fftconv_kernel(const float* __restrict__ x, const float* __restrict__ f,
               float* __restrict__ out) {
    extern __shared__ float2 sm[];   // NFFT float2 = 128 KB
    const int row = blockIdx.x;
    const int b   = row / DCH;
    const int t   = threadIdx.x;
    const float* __restrict__ xr = x + (size_t)row * LSEQ;
    const float* __restrict__ fr = f + (size_t)row * LSEQ;

    float2 v[16];

    // ---- Load (pattern e = t + 1024j), pack z = x + i*f; upper half zero ----
    #pragma unroll
    for (int j = 0; j < 8; j++) {
        int e = t + 1024 * j;
        v[j] = make_float2(xr[e], fr[e]);
    }

    // ---- Forward FFT (DIF, natural -> bit-reversed) ----
    dif4_zero(v, d_tw[t]);                             // stages 0-3, stride 1024
    #pragma unroll
    for (int j = 0; j < 16; j++) sm[sw(t + 1024 * j)] = v[j];
    __syncthreads();
    {
        int g = t >> 6, r = t & 63, base = g * 1024 + r;
        #pragma unroll
        for (int j = 0; j < 16; j++) v[j] = sm[sw(base + 64 * j)];
        dif4(v, d_tw[r << 4]);                         // stages 4-7, stride 64
        #pragma unroll
        for (int j = 0; j < 16; j++) sm[sw(base + 64 * j)] = v[j];
    }
    __syncthreads();
    {
        int h = t >> 2, q = t & 3, base = h * 64 + q;
        #pragma unroll
        for (int j = 0; j < 16; j++) v[j] = sm[sw(base + 4 * j)];
        dif4(v, d_tw[q << 8]);                         // stages 8-11, stride 4
        #pragma unroll
        for (int j = 0; j < 16; j++) sm[sw(base + 4 * j)] = v[j];
    }
    __syncthreads();

    // ---- FUSED: fwd stages 12-13 + pointwise + inv stages 0-1, all in regs ----
    // 4-block B holds spectrum bins k == k0 (mod 4096) with k0 = brev12(B);
    // block pair: B (even) <-> B' = brev12(4096 - k0), elementwise A[j] <-> B'[3-j].
    // Unit u in [0,2048) owns even block 2u; lanes own u's low 5 bits (bank spread).
    const float scale = 1.0f / ((float)NFFT * (float)NFFT);
    {
        int w = t >> 5, l = t & 31;
        #pragma unroll
        for (int m = 0; m < 2; m++) {
            int u = ((2 * w + m) << 5) | l;
            float2 a[4], c[4];
            if (u == 0) {
                // Special: self-paired blocks 0 (k0=0) and 1 (k0=2048).
                #pragma unroll
                for (int j = 0; j < 4; j++) { a[j] = sm[sw(j)]; c[j] = sm[sw(4 + j)]; }
                dif2(a); dif2(c);
                pws(a[0], scale);          // k = 0
                pws(a[1], scale);          // k = 8192
                pw(a[2], a[3], scale);     // k = 4096 <-> 12288
                pw(c[0], c[3], scale);     // k = 2048 <-> 14336
                pw(c[1], c[2], scale);     // k = 10240 <-> 6144
                dit2(a); dit2(c);
                #pragma unroll
                for (int j = 0; j < 4; j++) { sm[sw(j)] = a[j]; sm[sw(4 + j)] = c[j]; }
            } else {
                int BA = 2 * u;
                int k0 = __brev(BA) >> 20;                 // brev12
                int BB = __brev(4096 - k0) >> 20;          // partner (odd) block
                #pragma unroll
                for (int j = 0; j < 4; j++) {
                    a[j] = sm[sw(4 * BA + j)];
                    c[j] = sm[sw(4 * BB + j)];
                }
                dif2(a); dif2(c);
                pw(a[0], c[3], scale);
                pw(a[1], c[2], scale);
                pw(a[2], c[1], scale);
                pw(a[3], c[0], scale);
                dit2(a); dit2(c);
                #pragma unroll
                for (int j = 0; j < 4; j++) {
                    sm[sw(4 * BA + j)] = a[j];
                    sm[sw(4 * BB + j)] = c[j];
                }
            }
        }
    }
    __syncthreads();

    // ---- Inverse FFT (DIT, bit-reversed -> natural, unnormalized) ----
    {
        int h = t >> 2, q = t & 3, base = h * 64 + q;
        #pragma unroll
        for (int j = 0; j < 16; j++) v[j] = sm[sw(base + 4 * j)];
        dit4(v, d_tw[q << 8]);                         // stages 2-5, stride 4
        #pragma unroll
        for (int j = 0; j < 16; j++) sm[sw(base + 4 * j)] = v[j];
    }
    __syncthreads();
    {
        int g = t >> 6, r = t & 63, base = g * 1024 + r;
        #pragma unroll
        for (int j = 0; j < 16; j++) v[j] = sm[sw(base + 64 * j)];
        dit4(v, d_tw[r << 4]);                         // stages 6-9, stride 64
        #pragma unroll
        for (int j = 0; j < 16; j++) sm[sw(base + 64 * j)] = v[j];
    }
    __syncthreads();
    {
        #pragma unroll
        for (int j = 0; j < 16; j++) v[j] = sm[sw(t + 1024 * j)];
        dit4(v, d_tw[t]);                              // stages 10-13, stride 1024

        // ---- Store first LSEQ real samples, masked ----
        #pragma unroll
        for (int j = 0; j < 8; j++) {
            int l = t + 1024 * j;
            out[(size_t)row * LSEQ + l] = d_mask[b * LSEQ + l] * v[j].x;
        }
    }
}

extern "C" void kernel_launch(void* const* d_in, const int* in_sizes, int n_in,
                              void* d_out, int out_size) {
    const float* x   = (const float*)d_in[0];
    const float* f   = (const float*)d_in[1];
    const int*   pos = (const int*)d_in[2];
    float*       out = (float*)d_out;

    cudaFuncSetAttribute(fftconv_kernel,
                         cudaFuncAttributeMaxDynamicSharedMemorySize,
                         NFFT * sizeof(float2));

    setup_kernel<<<(8 * LSEQ) / 256, 256>>>(pos);
    fftconv_kernel<<<NROWS, NT, NFFT * sizeof(float2)>>>(x, f, out);
}